// round 11
// baseline (speedup 1.0000x reference)
#include <cuda_runtime.h>
#include <math.h>

// ROI max pooling, bit-exact vs JAX/XLA reference (contract proven in R2):
//   coords * 0.0625f -> __float2int_rn (round-half-even)
//   bin = roi_size * RN(1/7)   (XLA folds /7 into *recip)
//   floor/ceil edges, clip [0,50], empty bin -> 0.
//
// R11 structure:
//   K1: float4-vectorized NCHW->NHWC transpose into g_scr.
//   K2: grid (M, 7), block 224 = 7 warps, 8 blocks/SM. warp = pw bin,
//       256 channels (2x float4/lane). Gather loop FLATTENED over cells
//       with uniform row-wrap + unroll 4 -> 8 independent loads in flight
//       per chain regardless of bin row length. Smem-staged ordered
//       epilogue (R8: scattered global stores serialize in LTS).

static constexpr int   kC    = 256;
static constexpr int   kH    = 50;
static constexpr int   kW    = 50;
static constexpr int   kHW   = kH * kW;        // 2500
static constexpr int   kBins = 49;
static constexpr float kScale = 0.0625f;

__device__ float g_scr[4 * kHW * kC];          // 10.24 MB channels-last scratch

// ---------------- K1: NCHW -> NHWC transpose, float4 both sides
__global__ void __launch_bounds__(256)
transpose_kernel(const float* __restrict__ x)
{
    __shared__ float tile[32][36];             // pad 36: conflict-free, 16B-aligned rows
    const int b   = blockIdx.z;
    const int hw0 = blockIdx.x * 32;
    const int c0  = blockIdx.y * 32;
    const int t   = threadIdx.x;

    {
        const int q = t & 7;
        const int c = t >> 3;
        const int hw = hw0 + 4 * q;
        if (hw < kHW) {
            const float4 f = *(const float4*)
                (x + ((size_t)b * kC + c0 + c) * kHW + hw);
            *(float4*)&tile[c][4 * q] = f;
        }
    }
    __syncthreads();
    {
        const int cq  = t & 7;
        const int hwi = t >> 3;
        const int hw  = hw0 + hwi;
        if (hw < kHW) {
            float4 f;
            f.x = tile[4 * cq + 0][hwi];
            f.y = tile[4 * cq + 1][hwi];
            f.z = tile[4 * cq + 2][hwi];
            f.w = tile[4 * cq + 3][hwi];
            *(float4*)(g_scr + ((size_t)b * kHW + hw) * kC + c0 + 4 * cq) = f;
        }
    }
}

// ---------------- K2: one bin per warp, 256 channels per warp
__global__ void __launch_bounds__(224, 8)
roi_pool_nhwc(const float* __restrict__ rois,
              float* __restrict__ out)
{
    __shared__ __align__(16) float sout[kC * 7];       // 7168 B

    const int m    = blockIdx.x;               // ROI
    const int ph   = blockIdx.y;               // 0..6
    const int t    = threadIdx.x;
    const int lane = t & 31;
    const int pw   = t >> 5;                   // warp id = bin column 0..6

    const float* r = rois + (size_t)m * 5;

    // Uniform per-warp bin bounds (every lane computes the same values).
    const int b  = (int)r[0];
    const int x1 = __float2int_rn(r[1] * kScale);
    const int y1 = __float2int_rn(r[2] * kScale);
    const int x2 = __float2int_rn(r[3] * kScale);
    const int y2 = __float2int_rn(r[4] * kScale);

    const float roi_h = (float)max(y2 - y1 + 1, 1);
    const float roi_w = (float)max(x2 - x1 + 1, 1);
    const float kInv7 = 1.0f / 7.0f;           // RN(1/7), matches XLA
    const float bh = roi_h * kInv7;
    const float bw = roi_w * kInv7;

    const int hs = min(max((int)floorf((float)ph * bh)       + y1, 0), kH);
    const int he = min(max((int)ceilf((float)(ph + 1) * bh)  + y1, 0), kH);
    const int ws = min(max((int)floorf((float)pw * bw)       + x1, 0), kW);
    const int we = min(max((int)ceilf((float)(pw + 1) * bw)  + x1, 0), kW);

    const int span_h = max(he - hs, 0);
    const int span_w = max(we - ws, 0);
    const int ncells = span_h * span_w;

    // lane's two channel quads: c = 4*lane.. and c = 128+4*lane..
    const float4* __restrict__ p =
        (const float4*)g_scr + (size_t)b * (kHW * kC / 4)
        + (size_t)(hs * kW + ws) * 64 + lane;

    float v0 = -INFINITY, v1 = -INFINITY, v2 = -INFINITY, v3 = -INFINITY;
    float u0 = -INFINITY, u1 = -INFINITY, u2 = -INFINITY, u3 = -INFINITY;

    // Flattened cell loop: uniform wrap branch, unroll 4 for deep MLP.
    int wrem = span_w;
    const int rowskip = (kW - span_w) * 64;
    #pragma unroll 4
    for (int i = 0; i < ncells; ++i) {
        const float4 f = __ldg(p);              // channels 4*lane..+3
        const float4 g = __ldg(p + 32);         // channels 128+4*lane..+3
        v0 = fmaxf(v0, f.x); v1 = fmaxf(v1, f.y);
        v2 = fmaxf(v2, f.z); v3 = fmaxf(v3, f.w);
        u0 = fmaxf(u0, g.x); u1 = fmaxf(u1, g.y);
        u2 = fmaxf(u2, g.z); u3 = fmaxf(u3, g.w);
        p += 64;
        if (--wrem == 0) { wrem = span_w; p += rowskip; }
    }

    const bool valid = ncells > 0;
    float* s = sout + (4 * lane) * 7 + pw;      // c-major staging
    s[0 * 7] = valid ? v0 : 0.0f;
    s[1 * 7] = valid ? v1 : 0.0f;
    s[2 * 7] = valid ? v2 : 0.0f;
    s[3 * 7] = valid ? v3 : 0.0f;
    float* s2 = s + 128 * 7;
    s2[0 * 7] = valid ? u0 : 0.0f;
    s2[1 * 7] = valid ? u1 : 0.0f;
    s2[2 * 7] = valid ? u2 : 0.0f;
    s2[3 * 7] = valid ? u3 : 0.0f;
    __syncthreads();

    // Block's out slice: {m, c, ph, j} for all c, j -> ordered copy.
    float* __restrict__ obase = out + (size_t)m * (kC * kBins) + ph * 7;
    #pragma unroll
    for (int k = t; k < kC * 7; k += 224) {     // 8 iterations
        const int c = k / 7;
        const int j = k - c * 7;
        obase[c * kBins + j] = sout[k];
    }
}

extern "C" void kernel_launch(void* const* d_in, const int* in_sizes, int n_in,
                              void* d_out, int out_size)
{
    const float* x    = (const float*)d_in[0];
    const float* rois = (const float*)d_in[1];
    float*       out  = (float*)d_out;

    const int B = in_sizes[0] / (kC * kHW);
    const int M = in_sizes[1] / 5;

    dim3 tgrid((kHW + 31) / 32, kC / 32, B);   // (79, 8, B)
    transpose_kernel<<<tgrid, 256>>>(x);

    dim3 pgrid(M, 7);                          // 1792 blocks x 7 warps
    roi_pool_nhwc<<<pgrid, 224>>>(rois, out);
}

// round 12
// speedup vs baseline: 1.1191x; 1.1191x over previous
#include <cuda_runtime.h>
#include <math.h>

// ROI max pooling, bit-exact vs JAX/XLA reference (contract proven in R2):
//   coords * 0.0625f -> __float2int_rn (round-half-even)
//   bin = roi_size * RN(1/7)   (XLA folds /7 into *recip)
//   floor/ceil edges, clip [0,50], empty bin -> 0.
//
// R12 structure (= R10 + dual-row load chains):
//   K1: float4-vectorized NCHW->NHWC transpose into g_scr.
//   K2: grid (M, 7), block 224 = 7 warps. warp = pw bin, 256 channels
//       (2x float4/lane). Inner gather processes TWO h-rows with
//       independent pointers -> 4 independent LDG.128 per iteration
//       (R11 showed data-dependent wrap kills load batching; this keeps
//       control flow static). Smem-staged ordered epilogue (R8 lesson).

static constexpr int   kC    = 256;
static constexpr int   kH    = 50;
static constexpr int   kW    = 50;
static constexpr int   kHW   = kH * kW;        // 2500
static constexpr int   kBins = 49;
static constexpr float kScale = 0.0625f;

__device__ float g_scr[4 * kHW * kC];          // 10.24 MB channels-last scratch

// ---------------- K1: NCHW -> NHWC transpose, float4 both sides
__global__ void __launch_bounds__(256)
transpose_kernel(const float* __restrict__ x)
{
    __shared__ float tile[32][36];             // pad 36: conflict-free, 16B rows
    const int b   = blockIdx.z;
    const int hw0 = blockIdx.x * 32;
    const int c0  = blockIdx.y * 32;
    const int t   = threadIdx.x;

    {
        const int q = t & 7;
        const int c = t >> 3;
        const int hw = hw0 + 4 * q;
        if (hw < kHW) {
            const float4 f = *(const float4*)
                (x + ((size_t)b * kC + c0 + c) * kHW + hw);
            *(float4*)&tile[c][4 * q] = f;
        }
    }
    __syncthreads();
    {
        const int cq  = t & 7;
        const int hwi = t >> 3;
        const int hw  = hw0 + hwi;
        if (hw < kHW) {
            float4 f;
            f.x = tile[4 * cq + 0][hwi];
            f.y = tile[4 * cq + 1][hwi];
            f.z = tile[4 * cq + 2][hwi];
            f.w = tile[4 * cq + 3][hwi];
            *(float4*)(g_scr + ((size_t)b * kHW + hw) * kC + c0 + 4 * cq) = f;
        }
    }
}

// ---------------- K2: one bin per warp, 256 channels per warp
__global__ void __launch_bounds__(224)
roi_pool_nhwc(const float* __restrict__ rois,
              float* __restrict__ out)
{
    __shared__ __align__(16) float sout[kC * 7];       // 7168 B

    const int m    = blockIdx.x;               // ROI
    const int ph   = blockIdx.y;               // 0..6
    const int t    = threadIdx.x;
    const int lane = t & 31;
    const int pw   = t >> 5;                   // warp id = bin column 0..6

    const float* r = rois + (size_t)m * 5;

    // Uniform per-warp bin bounds (every lane computes the same values).
    const int b  = (int)r[0];
    const int x1 = __float2int_rn(r[1] * kScale);
    const int y1 = __float2int_rn(r[2] * kScale);
    const int x2 = __float2int_rn(r[3] * kScale);
    const int y2 = __float2int_rn(r[4] * kScale);

    const float roi_h = (float)max(y2 - y1 + 1, 1);
    const float roi_w = (float)max(x2 - x1 + 1, 1);
    const float kInv7 = 1.0f / 7.0f;           // RN(1/7), matches XLA
    const float bh = roi_h * kInv7;
    const float bw = roi_w * kInv7;

    const int hs = min(max((int)floorf((float)ph * bh)       + y1, 0), kH);
    const int he = min(max((int)ceilf((float)(ph + 1) * bh)  + y1, 0), kH);
    const int ws = min(max((int)floorf((float)pw * bw)       + x1, 0), kW);
    const int we = min(max((int)ceilf((float)(pw + 1) * bw)  + x1, 0), kW);

    // lane's two channel quads: c = 4*lane.. and c = 128+4*lane..
    const float4* __restrict__ base4 =
        (const float4*)g_scr + (size_t)b * (kHW * kC / 4) + lane;

    float v0 = -INFINITY, v1 = -INFINITY, v2 = -INFINITY, v3 = -INFINITY;
    float u0 = -INFINITY, u1 = -INFINITY, u2 = -INFINITY, u3 = -INFINITY;

    int h = hs;
    // Dual-row passes: two independent pointer chains, 4 loads/iteration.
    for (; h + 1 < he; h += 2) {
        const float4* __restrict__ p0 = base4 + (size_t)(h * kW + ws) * 64;
        const float4* __restrict__ p1 = p0 + (size_t)kW * 64;
        #pragma unroll 2
        for (int w = ws; w < we; ++w) {
            const float4 f0 = __ldg(p0);
            const float4 g0 = __ldg(p0 + 32);
            const float4 f1 = __ldg(p1);
            const float4 g1 = __ldg(p1 + 32);
            v0 = fmaxf(fmaxf(v0, f0.x), f1.x);
            v1 = fmaxf(fmaxf(v1, f0.y), f1.y);
            v2 = fmaxf(fmaxf(v2, f0.z), f1.z);
            v3 = fmaxf(fmaxf(v3, f0.w), f1.w);
            u0 = fmaxf(fmaxf(u0, g0.x), g1.x);
            u1 = fmaxf(fmaxf(u1, g0.y), g1.y);
            u2 = fmaxf(fmaxf(u2, g0.z), g1.z);
            u3 = fmaxf(fmaxf(u3, g0.w), g1.w);
            p0 += 64; p1 += 64;
        }
    }
    // Tail row (span_h odd): R10's exact loop.
    if (h < he) {
        const float4* __restrict__ p = base4 + (size_t)(h * kW + ws) * 64;
        #pragma unroll 2
        for (int w = ws; w < we; ++w) {
            const float4 f = __ldg(p);
            const float4 g = __ldg(p + 32);
            v0 = fmaxf(v0, f.x); v1 = fmaxf(v1, f.y);
            v2 = fmaxf(v2, f.z); v3 = fmaxf(v3, f.w);
            u0 = fmaxf(u0, g.x); u1 = fmaxf(u1, g.y);
            u2 = fmaxf(u2, g.z); u3 = fmaxf(u3, g.w);
            p += 64;
        }
    }

    const bool valid = (he > hs) && (we > ws);
    float* s = sout + (4 * lane) * 7 + pw;      // c-major staging
    s[0 * 7] = valid ? v0 : 0.0f;
    s[1 * 7] = valid ? v1 : 0.0f;
    s[2 * 7] = valid ? v2 : 0.0f;
    s[3 * 7] = valid ? v3 : 0.0f;
    float* s2 = s + 128 * 7;
    s2[0 * 7] = valid ? u0 : 0.0f;
    s2[1 * 7] = valid ? u1 : 0.0f;
    s2[2 * 7] = valid ? u2 : 0.0f;
    s2[3 * 7] = valid ? u3 : 0.0f;
    __syncthreads();

    // Block's out slice: {m, c, ph, j} for all c, j -> ordered copy.
    float* __restrict__ obase = out + (size_t)m * (kC * kBins) + ph * 7;
    #pragma unroll
    for (int k = t; k < kC * 7; k += 224) {     // 8 iterations
        const int c = k / 7;
        const int j = k - c * 7;
        obase[c * kBins + j] = sout[k];
    }
}

extern "C" void kernel_launch(void* const* d_in, const int* in_sizes, int n_in,
                              void* d_out, int out_size)
{
    const float* x    = (const float*)d_in[0];
    const float* rois = (const float*)d_in[1];
    float*       out  = (float*)d_out;

    const int B = in_sizes[0] / (kC * kHW);
    const int M = in_sizes[1] / 5;

    dim3 tgrid((kHW + 31) / 32, kC / 32, B);   // (79, 8, B)
    transpose_kernel<<<tgrid, 256>>>(x);

    dim3 pgrid(M, 7);                          // 1792 blocks x 7 warps
    roi_pool_nhwc<<<pgrid, 224>>>(rois, out);
}

// round 13
// speedup vs baseline: 1.1212x; 1.0019x over previous
#include <cuda_runtime.h>
#include <math.h>

// ROI max pooling, bit-exact vs JAX/XLA reference (contract proven in R2):
//   coords * 0.0625f -> __float2int_rn (round-half-even)
//   bin = roi_size * RN(1/7)   (XLA folds /7 into *recip)
//   floor/ceil edges, clip [0,50], empty bin -> 0.
//
// R13 structure:
//   K1: NCHW->NHWC transpose, 32c x 128hw tiles (640 blocks), float4 gmem
//       both sides, scalar smem with pad-133 (conflict-free both phases).
//   K2: = R10 champion (one bin/warp, 256 ch, smem-staged ordered epilogue)
//       + warp-uniform specialization on span_w (1 / 2 / generic) so the
//       inner load count is static and ptxas can front-batch LDGs.

static constexpr int   kC    = 256;
static constexpr int   kH    = 50;
static constexpr int   kW    = 50;
static constexpr int   kHW   = kH * kW;        // 2500
static constexpr int   kBins = 49;
static constexpr float kScale = 0.0625f;

__device__ float g_scr[4 * kHW * kC];          // 10.24 MB channels-last scratch

// ---------------- K1: NCHW -> NHWC transpose, 32c x 128hw tile
__global__ void __launch_bounds__(256)
transpose_kernel(const float* __restrict__ x)
{
    __shared__ float tile[32][133];            // pad 133: conflict-free scalar
    const int b   = blockIdx.z;
    const int hw0 = blockIdx.x * 128;
    const int c0  = blockIdx.y * 32;
    const int t   = threadIdx.x;

    // Load: thread (q = t&7, c = t>>3) handles float4s at hw0 + 4*(q + 8k)
    {
        const int q = t & 7;
        const int c = t >> 3;
        const float* src = x + ((size_t)b * kC + c0 + c) * kHW;
        #pragma unroll
        for (int k = 0; k < 4; ++k) {
            const int hwl = 4 * (q + 8 * k);
            const int hw  = hw0 + hwl;
            if (hw + 3 < kHW) {
                const float4 f = *(const float4*)(src + hw);
                tile[c][hwl + 0] = f.x;
                tile[c][hwl + 1] = f.y;
                tile[c][hwl + 2] = f.z;
                tile[c][hwl + 3] = f.w;
            } else {
                for (int e = 0; e < 4; ++e)
                    if (hw + e < kHW) tile[c][hwl + e] = src[hw + e];
            }
        }
    }
    __syncthreads();

    // Store: thread (cq = t&7, base hwi = t>>3) writes float4 of channels
    // c0+4cq..+3 at positions hw0 + (t>>3) + 32k.
    {
        const int cq = t & 7;
        #pragma unroll
        for (int k = 0; k < 4; ++k) {
            const int hwi = (t >> 3) + 32 * k;
            const int hw  = hw0 + hwi;
            if (hw < kHW) {
                float4 f;
                f.x = tile[4 * cq + 0][hwi];
                f.y = tile[4 * cq + 1][hwi];
                f.z = tile[4 * cq + 2][hwi];
                f.w = tile[4 * cq + 3][hwi];
                *(float4*)(g_scr + ((size_t)b * kHW + hw) * kC + c0 + 4 * cq) = f;
            }
        }
    }
}

// ---------------- K2: one bin per warp, 256 channels per warp
__global__ void __launch_bounds__(224)
roi_pool_nhwc(const float* __restrict__ rois,
              float* __restrict__ out)
{
    __shared__ __align__(16) float sout[kC * 7];       // 7168 B

    const int m    = blockIdx.x;               // ROI
    const int ph   = blockIdx.y;               // 0..6
    const int t    = threadIdx.x;
    const int lane = t & 31;
    const int pw   = t >> 5;                   // warp id = bin column 0..6

    const float* r = rois + (size_t)m * 5;

    // Uniform per-warp bin bounds (every lane computes the same values).
    const int b  = (int)r[0];
    const int x1 = __float2int_rn(r[1] * kScale);
    const int y1 = __float2int_rn(r[2] * kScale);
    const int x2 = __float2int_rn(r[3] * kScale);
    const int y2 = __float2int_rn(r[4] * kScale);

    const float roi_h = (float)max(y2 - y1 + 1, 1);
    const float roi_w = (float)max(x2 - x1 + 1, 1);
    const float kInv7 = 1.0f / 7.0f;           // RN(1/7), matches XLA
    const float bh = roi_h * kInv7;
    const float bw = roi_w * kInv7;

    const int hs = min(max((int)floorf((float)ph * bh)       + y1, 0), kH);
    const int he = min(max((int)ceilf((float)(ph + 1) * bh)  + y1, 0), kH);
    const int ws = min(max((int)floorf((float)pw * bw)       + x1, 0), kW);
    const int we = min(max((int)ceilf((float)(pw + 1) * bw)  + x1, 0), kW);

    // lane's two channel quads: c = 4*lane.. and c = 128+4*lane..
    const float4* __restrict__ base4 =
        (const float4*)g_scr + (size_t)b * (kHW * kC / 4) + lane;

    float v0 = -INFINITY, v1 = -INFINITY, v2 = -INFINITY, v3 = -INFINITY;
    float u0 = -INFINITY, u1 = -INFINITY, u2 = -INFINITY, u3 = -INFINITY;

    const int span_w = we - ws;
    if (span_w == 1) {
        // Most common narrow case: 2 independent loads per h, static body.
        #pragma unroll 2
        for (int h = hs; h < he; ++h) {
            const float4* __restrict__ p = base4 + (size_t)(h * kW + ws) * 64;
            const float4 f = __ldg(p);
            const float4 g = __ldg(p + 32);
            v0 = fmaxf(v0, f.x); v1 = fmaxf(v1, f.y);
            v2 = fmaxf(v2, f.z); v3 = fmaxf(v3, f.w);
            u0 = fmaxf(u0, g.x); u1 = fmaxf(u1, g.y);
            u2 = fmaxf(u2, g.z); u3 = fmaxf(u3, g.w);
        }
    } else if (span_w == 2) {
        // 4 independent loads per h, static body.
        #pragma unroll 2
        for (int h = hs; h < he; ++h) {
            const float4* __restrict__ p = base4 + (size_t)(h * kW + ws) * 64;
            const float4 f0 = __ldg(p);
            const float4 g0 = __ldg(p + 32);
            const float4 f1 = __ldg(p + 64);
            const float4 g1 = __ldg(p + 96);
            v0 = fmaxf(fmaxf(v0, f0.x), f1.x);
            v1 = fmaxf(fmaxf(v1, f0.y), f1.y);
            v2 = fmaxf(fmaxf(v2, f0.z), f1.z);
            v3 = fmaxf(fmaxf(v3, f0.w), f1.w);
            u0 = fmaxf(fmaxf(u0, g0.x), g1.x);
            u1 = fmaxf(fmaxf(u1, g0.y), g1.y);
            u2 = fmaxf(fmaxf(u2, g0.z), g1.z);
            u3 = fmaxf(fmaxf(u3, g0.w), g1.w);
        }
    } else if (span_w > 2) {
        // Generic wide case (R10 champion loop).
        for (int h = hs; h < he; ++h) {
            const float4* __restrict__ p = base4 + (size_t)(h * kW + ws) * 64;
            #pragma unroll 2
            for (int w = ws; w < we; ++w) {
                const float4 f = __ldg(p);
                const float4 g = __ldg(p + 32);
                v0 = fmaxf(v0, f.x); v1 = fmaxf(v1, f.y);
                v2 = fmaxf(v2, f.z); v3 = fmaxf(v3, f.w);
                u0 = fmaxf(u0, g.x); u1 = fmaxf(u1, g.y);
                u2 = fmaxf(u2, g.z); u3 = fmaxf(u3, g.w);
                p += 64;
            }
        }
    }

    const bool valid = (he > hs) && (we > ws);
    float* s = sout + (4 * lane) * 7 + pw;      // c-major staging
    s[0 * 7] = valid ? v0 : 0.0f;
    s[1 * 7] = valid ? v1 : 0.0f;
    s[2 * 7] = valid ? v2 : 0.0f;
    s[3 * 7] = valid ? v3 : 0.0f;
    float* s2 = s + 128 * 7;
    s2[0 * 7] = valid ? u0 : 0.0f;
    s2[1 * 7] = valid ? u1 : 0.0f;
    s2[2 * 7] = valid ? u2 : 0.0f;
    s2[3 * 7] = valid ? u3 : 0.0f;
    __syncthreads();

    // Block's out slice: {m, c, ph, j} for all c, j -> ordered copy.
    float* __restrict__ obase = out + (size_t)m * (kC * kBins) + ph * 7;
    #pragma unroll
    for (int k = t; k < kC * 7; k += 224) {     // 8 iterations
        const int c = k / 7;
        const int j = k - c * 7;
        obase[c * kBins + j] = sout[k];
    }
}

extern "C" void kernel_launch(void* const* d_in, const int* in_sizes, int n_in,
                              void* d_out, int out_size)
{
    const float* x    = (const float*)d_in[0];
    const float* rois = (const float*)d_in[1];
    float*       out  = (float*)d_out;

    const int B = in_sizes[0] / (kC * kHW);
    const int M = in_sizes[1] / 5;

    dim3 tgrid((kHW + 127) / 128, kC / 32, B); // (20, 8, B) = 640 blocks
    transpose_kernel<<<tgrid, 256>>>(x);

    dim3 pgrid(M, 7);                          // 1792 blocks x 7 warps
    roi_pool_nhwc<<<pgrid, 224>>>(rois, out);
}